// round 11
// baseline (speedup 1.0000x reference)
#include <cuda_runtime.h>
#include <cuda_bf16.h>
#include <math.h>

// Problem constants (fixed by setup_inputs)
#define NPTS 32768
#define NV   10475
#define NJ   55
#define KNN  6

// Template binning: 2D (x,y). Point binning: 3D (x,y,z-coarse).
#define NBX  128
#define NBY  128
#define NBZ  16
#define NB2  (NBX * NBY)          // 16384
#define NB3  (NB2 * NBZ)          // 262144
#define BW   0.15625f             // 20/128, exact in fp32
#define BINV2 6.4f
#define BINVZ 0.8f                // 16/20
#define XLIM 10.0f
#define SEPS 1e-3f                // screen slack in s-units
#define DELTA0 0.40f              // sized to typical sqrt(d6)

typedef unsigned long long u64;
#define KSENT 0xFFFFFFFFFFFFFFFFull

// Scratch (no cudaMalloc allowed).
__device__ int    g_tcnt[NB2], g_tstart[NB2 + 1], g_tcur[NB2];
__device__ int    g_pcnt[NB3], g_pstart[NB3 + 1], g_pcur[NB3];
__device__ float4 g_tsorted[NV + 8];      // {x, y, z, -t2/2}
__device__ int    g_tidx  [NV + 8];
__device__ float4 g_psorted[NPTS];        // {x, y, z, orig_point_idx}
__device__ int    g_knn_idx[NPTS * KNN];
__device__ float  g_knn_d  [NPTS * KNN];

__device__ __forceinline__ int bin1(float x) {
    return min(NBX - 1, max(0, (int)((x + XLIM) * BINV2)));
}
__device__ __forceinline__ int binz(float z) {
    return min(NBZ - 1, max(0, (int)((z + XLIM) * BINVZ)));
}
// 3D point key with serpentine y (on x parity) and serpentine z (on y parity)
__device__ __forceinline__ int pkey(float x, float y, float z) {
    int kx = bin1(x), ky = bin1(y), kz = binz(z);
    if (kx & 1) ky = NBY - 1 - ky;
    if (ky & 1) kz = NBZ - 1 - kz;
    return (kx * NBY + ky) * NBZ + kz;
}

// Exact reference-rounded d2 (verified R3-R10), clamped BEFORE selection,
// packed with the original index into a scan-order-independent sortable key.
__device__ __forceinline__ u64 cand_key(float4 t, int oidx,
                                        float px, float py, float pz, float p2) {
    float t2 = -2.0f * t.w;               // exact
    float cross = __fmaf_rn(pz, t.z, __fmaf_rn(py, t.y, __fmul_rn(px, t.x)));
    float d2 = fmaxf(__fmaf_rn(-2.0f, cross, __fadd_rn(p2, t2)), 0.0f);
    return ((u64)__float_as_uint(d2) << 32) | (u64)(unsigned)oidx;
}

__device__ __forceinline__ void key_insert(u64* K, u64 key) {
    if (key < K[KNN - 1]) {
        K[KNN - 1] = key;
#pragma unroll
        for (int k = KNN - 1; k > 0; --k)
            if (K[k] < K[k - 1]) { u64 t = K[k]; K[k] = K[k - 1]; K[k - 1] = t; }
    }
}

// ---------------------------------------------------------------------------
// Prep kernels
// ---------------------------------------------------------------------------
extern "C" __global__ void k_zero() {
    int i = blockIdx.x * blockDim.x + threadIdx.x;
    for (int j = i; j < NB2; j += gridDim.x * blockDim.x) g_tcnt[j] = 0;
    for (int j = i; j < NB3; j += gridDim.x * blockDim.x) g_pcnt[j] = 0;
}

extern "C" __global__ void k_hist(const float* __restrict__ tpts,
                                  const float* __restrict__ pts) {
    int i = blockIdx.x * blockDim.x + threadIdx.x;
    if (i < NV) {
        int bx = bin1(tpts[3*i]), by = bin1(tpts[3*i+1]);
        atomicAdd(&g_tcnt[bx * NBY + by], 1);
    }
    if (i < NPTS)
        atomicAdd(&g_pcnt[pkey(pts[3*i], pts[3*i+1], pts[3*i+2])], 1);
}

extern "C" __global__ void __launch_bounds__(1024) k_scan() {
    __shared__ int sA[1024], sB[1024];
    const int t = threadIdx.x;
#pragma unroll 1
    for (int w = 0; w < 2; ++w) {
        const int* cnt = w ? g_pcnt : g_tcnt;
        int* start = w ? g_pstart : g_tstart;
        int* cur   = w ? g_pcur   : g_tcur;
        const int NBw = w ? NB3 : NB2;
        const int C = NBw / 1024;
        int sum = 0;
        for (int i = 0; i < C; ++i) sum += cnt[t * C + i];
        sA[t] = sum; __syncthreads();
        int *src = sA, *dst = sB;
        for (int off = 1; off < 1024; off <<= 1) {
            int v = src[t] + ((t >= off) ? src[t - off] : 0);
            dst[t] = v; __syncthreads();
            int* tmp = src; src = dst; dst = tmp;
        }
        int run = src[t] - sum;
        for (int i = 0; i < C; ++i) {
            int id = t * C + i;
            start[id] = run; cur[id] = run;
            run += cnt[id];
        }
        if (t == 1023) start[NBw] = run;
        __syncthreads();
    }
}

extern "C" __global__ void k_scatter(const float* __restrict__ tpts,
                                     const float* __restrict__ pts) {
    int i = blockIdx.x * blockDim.x + threadIdx.x;
    if (i < NV) {
        float x = tpts[3*i], y = tpts[3*i+1], z = tpts[3*i+2];
        float t2 = __fadd_rn(__fadd_rn(__fmul_rn(x, x), __fmul_rn(y, y)),
                             __fmul_rn(z, z));
        int pos = atomicAdd(&g_tcur[bin1(x) * NBY + bin1(y)], 1);
        g_tsorted[pos] = make_float4(x, y, z, -0.5f * t2);
        g_tidx[pos] = i;
    }
    if (i >= NV && i < NV + 8) {          // pad
        g_tsorted[i] = make_float4(0.f, 0.f, 0.f, -INFINITY);
        g_tidx[i] = 0;
    }
    if (i < NPTS) {
        float x = pts[3*i], y = pts[3*i+1], z = pts[3*i+2];
        int pos = atomicAdd(&g_pcur[pkey(x, y, z)], 1);
        g_psorted[pos] = make_float4(x, y, z, __uint_as_float((unsigned)i));
    }
}

// ---------------------------------------------------------------------------
// Contiguous segment scan with screen (R4/R9-verified machinery).
// ---------------------------------------------------------------------------
__device__ __forceinline__ void scan_seg(
    const float4* __restrict__ st, const int* __restrict__ stidx,
    int s, int e, float px, float py, float pz, float p2,
    u64* K, float& s_thresh)
{
#pragma unroll 1
    for (int v0 = s; v0 < e; ) {
        const int ce = min(v0 + 64, e);
#pragma unroll 1
        for (; v0 < ce; v0 += 8) {
            float sc[8];
#pragma unroll
            for (int i = 0; i < 8; ++i) {
                float4 t = st[v0 + i];
                float v = fmaf(pz, t.z, fmaf(py, t.y, fmaf(px, t.x, t.w)));
                sc[i] = (v0 + i < ce) ? v : -INFINITY;
            }
            float m = fmaxf(fmaxf(fmaxf(sc[0], sc[1]), fmaxf(sc[2], sc[3])),
                            fmaxf(fmaxf(sc[4], sc[5]), fmaxf(sc[6], sc[7])));
            if (m > s_thresh) {
                unsigned pm = 0;
#pragma unroll
                for (int i = 0; i < 8; ++i)
                    pm |= (sc[i] > s_thresh) ? (1u << i) : 0u;
                while (pm) {
                    int i = __ffs(pm) - 1; pm &= pm - 1;
                    key_insert(K, cand_key(st[v0 + i], stidx[v0 + i],
                                           px, py, pz, p2));
                }
            }
        }
        if (K[KNN - 1] != KSENT) {
            float d6 = __uint_as_float((unsigned)(K[KNN - 1] >> 32));
            s_thresh = fmaf(-0.5f, d6, 0.5f * p2) - SEPS;
        }
    }
}

// ---------------------------------------------------------------------------
// Kernel B: adaptive 2D-windowed KNN with z-coherent warps.
// ---------------------------------------------------------------------------
extern "C" __global__ void __launch_bounds__(256, 1)
k_knn()
{
    extern __shared__ char smem[];
    float4* st    = (float4*)smem;                // NV+8
    int*    stidx = (int*)(st + NV + 8);          // NV+8

    for (int i = threadIdx.x; i < NV + 8; i += 256) {
        st[i] = g_tsorted[i]; stidx[i] = g_tidx[i];
    }
    __syncthreads();

    const int n = blockIdx.x * 256 + threadIdx.x;
    float4 P = g_psorted[n];
    float px = P.x, py = P.y, pz = P.z;
    unsigned pid = __float_as_uint(P.w);
    float p2 = __fadd_rn(__fadd_rn(__fmul_rn(px, px), __fmul_rn(py, py)),
                         __fmul_rn(pz, pz));

    // warp (x,y) hull
    float xlo = px, xhi = px, ylo = py, yhi = py;
#pragma unroll
    for (int off = 16; off >= 1; off >>= 1) {
        xlo = fminf(xlo, __shfl_xor_sync(0xFFFFFFFFu, xlo, off));
        xhi = fmaxf(xhi, __shfl_xor_sync(0xFFFFFFFFu, xhi, off));
        ylo = fminf(ylo, __shfl_xor_sync(0xFFFFFFFFu, ylo, off));
        yhi = fmaxf(yhi, __shfl_xor_sync(0xFFFFFFFFu, yhi, off));
    }

    u64 K[KNN];
#pragma unroll
    for (int k = 0; k < KNN; ++k) K[k] = KSENT;
    float s_thresh = -INFINITY;

    float delta = DELTA0;
    int bxlo = bin1(xlo - delta), bxhi = bin1(xhi + delta);
    int bylo = bin1(ylo - delta), byhi = bin1(yhi + delta);

    for (int bx = bxlo; bx <= bxhi; ++bx) {
        int s = __ldg(&g_tstart[bx * NBY + bylo]);
        int e = __ldg(&g_tstart[bx * NBY + byhi + 1]);
        scan_seg(st, stidx, s, e, px, py, pz, p2, K, s_thresh);
    }

#pragma unroll 1
    for (int it = 0; it < 16; ++it) {
        // Per-lane certification: unscanned templates are outside the window;
        // clamped grid edges contribute +inf.
        float bx_lo = (bxlo == 0)       ? 1e15f : px - ((float)bxlo * BW - XLIM);
        float bx_hi = (bxhi == NBX - 1) ? 1e15f : ((float)(bxhi + 1) * BW - XLIM) - px;
        float by_lo = (bylo == 0)       ? 1e15f : py - ((float)bylo * BW - XLIM);
        float by_hi = (byhi == NBY - 1) ? 1e15f : ((float)(byhi + 1) * BW - XLIM) - py;
        float bound = fminf(fminf(bx_lo, bx_hi), fminf(by_lo, by_hi));
        float d6 = __uint_as_float((unsigned)(K[KNN - 1] >> 32));
        bool have6 = (K[KNN - 1] != KSENT);
        bool done = have6 && (d6 <= 0.998f * bound * bound);
        if (__all_sync(0xFFFFFFFFu, done)) break;

        // Adaptive requirement: lane needs window half-width sqrt(d6).
        float need = have6 ? (__fsqrt_rn(d6) * 1.002f) : (delta * 2.0f);
#pragma unroll
        for (int off = 16; off >= 1; off >>= 1)
            need = fmaxf(need, __shfl_xor_sync(0xFFFFFFFFu, need, off));
        delta = fmaxf(need, delta + BW);      // guarantee >=1 bin growth

        int nbxlo = bin1(xlo - delta), nbxhi = bin1(xhi + delta);
        int nbylo = bin1(ylo - delta), nbyhi = bin1(yhi + delta);

        // new x strips: full new y-range
        for (int bx = nbxlo; bx < bxlo; ++bx) {
            int s = __ldg(&g_tstart[bx * NBY + nbylo]);
            int e = __ldg(&g_tstart[bx * NBY + nbyhi + 1]);
            scan_seg(st, stidx, s, e, px, py, pz, p2, K, s_thresh);
        }
        for (int bx = bxhi + 1; bx <= nbxhi; ++bx) {
            int s = __ldg(&g_tstart[bx * NBY + nbylo]);
            int e = __ldg(&g_tstart[bx * NBY + nbyhi + 1]);
            scan_seg(st, stidx, s, e, px, py, pz, p2, K, s_thresh);
        }
        // y extensions on the old x strip
        if (nbylo < bylo)
            for (int bx = bxlo; bx <= bxhi; ++bx) {
                int s = __ldg(&g_tstart[bx * NBY + nbylo]);
                int e = __ldg(&g_tstart[bx * NBY + bylo]);
                scan_seg(st, stidx, s, e, px, py, pz, p2, K, s_thresh);
            }
        if (nbyhi > byhi)
            for (int bx = bxlo; bx <= bxhi; ++bx) {
                int s = __ldg(&g_tstart[bx * NBY + byhi + 1]);
                int e = __ldg(&g_tstart[bx * NBY + nbyhi + 1]);
                scan_seg(st, stidx, s, e, px, py, pz, p2, K, s_thresh);
            }
        bxlo = nbxlo; bxhi = nbxhi; bylo = nbylo; byhi = nbyhi;
    }

#pragma unroll
    for (int k = 0; k < KNN; ++k) {
        g_knn_idx[pid * KNN + k] = (int)(unsigned)(K[k] & 0xFFFFFFFFull);
        g_knn_d  [pid * KNN + k] = __uint_as_float((unsigned)(K[k] >> 32));
    }
}

// ---------------------------------------------------------------------------
// Epilogue (unchanged, measured 17us). One warp = one point.
// ---------------------------------------------------------------------------
extern "C" __global__ void __launch_bounds__(256)
epilogue_kernel(const float* __restrict__ lbs,   // (V,55)
                const float* __restrict__ vt,    // (V,16)
                float* __restrict__ out)         // [N dist | N*16 transform]
{
    int gwarp = (blockIdx.x * blockDim.x + threadIdx.x) >> 5;
    int lane  = threadIdx.x & 31;

    int   idx[KNN];
    float d[KNN];
#pragma unroll
    for (int k = 0; k < KNN; ++k) {
        idx[k] = g_knn_idx[gwarp * KNN + k];
        d[k]   = g_knn_d  [gwarp * KNN + k];
    }

    const float* w0row = lbs + (long)idx[0] * NJ;
    float w0a = w0row[lane];
    float w0b = (lane < NJ - 32) ? w0row[lane + 32] : 0.0f;

    float conf[KNN];
    conf[0] = 1.0f;
#pragma unroll
    for (int k = 1; k < KNN; ++k) {
        const float* wr = lbs + (long)idx[k] * NJ;
        float a = fabsf(wr[lane] - w0a);
        if (lane < NJ - 32) a += fabsf(wr[lane + 32] - w0b);
#pragma unroll
        for (int off = 16; off >= 1; off >>= 1)
            a += __shfl_xor_sync(0xFFFFFFFFu, a, off);
        conf[k] = (expf(-a * (1.0f / 0.02f)) > 0.9f) ? 1.0f : 0.0f;
    }

    float w[KNN];
    float wsum = 0.0f;
#pragma unroll
    for (int k = 0; k < KNN; ++k) {
        w[k] = expf(-d[k]) * conf[k];
        wsum += w[k];
    }
    float inv = 1.0f / wsum;

    float xd  = 0.0f;
    float acc = 0.0f;
#pragma unroll
    for (int k = 0; k < KNN; ++k) {
        float wk = w[k] * inv;
        xd = fmaf(wk, d[k], xd);
        if (lane < 16)
            acc = fmaf(wk, vt[(long)idx[k] * 16 + lane], acc);
    }

    if (lane == 0) out[gwarp] = xd;
    if (lane < 16) out[NPTS + gwarp * 16 + lane] = acc;
}

// ---------------------------------------------------------------------------
// Launch. Inputs: lbs_weights, verts_transform, points, template_points, K.
// ---------------------------------------------------------------------------
extern "C" void kernel_launch(void* const* d_in, const int* in_sizes, int n_in,
                              void* d_out, int out_size)
{
    const float* lbs  = (const float*)d_in[0];
    const float* vt   = (const float*)d_in[1];
    const float* pts  = (const float*)d_in[2];
    const float* tpts = (const float*)d_in[3];
    float* out = (float*)d_out;

    const int smem_bytes = (NV + 8) * 16 + (NV + 8) * 4;   // ~210 KB
    cudaFuncSetAttribute(k_knn,
                         cudaFuncAttributeMaxDynamicSharedMemorySize,
                         smem_bytes);

    k_zero<<<256, 256>>>();
    k_hist<<<(NPTS + 255) / 256, 256>>>(tpts, pts);
    k_scan<<<1, 1024>>>();
    k_scatter<<<(NPTS + 255) / 256, 256>>>(tpts, pts);
    k_knn<<<NPTS / 256, 256, smem_bytes>>>();
    epilogue_kernel<<<(NPTS * 32) / 256, 256>>>(lbs, vt, out);
}

// round 12
// speedup vs baseline: 3.1247x; 3.1247x over previous
#include <cuda_runtime.h>
#include <cuda_bf16.h>
#include <math.h>

// Problem constants (fixed by setup_inputs)
#define NPTS 32768
#define NV   10475
#define NJ   55
#define KNN  6

// 1D x-binning (R9-verified)
#define NB    1024
#define BW    0.01953125f        // 20/1024, exact in fp32
#define BINV  51.2f
#define XLIM  10.0f
#define SEPS  1e-3f
#define DELTA0 0.2f

// Per-CTA staged template window
#define WCAP 4608                // float4 count; 73728 B -> 2 CTAs/SM
#define PAD  0.45f

typedef unsigned long long u64;
#define KSENT 0xFFFFFFFFFFFFFFFFull

// Scratch (no cudaMalloc allowed).
__device__ int    g_tbcnt[NB], g_tbstart[NB + 1], g_tbcur[NB];
__device__ int    g_pbcnt[NB], g_pbstart[NB + 1], g_pbcur[NB];
__device__ float4 g_tsorted[NV + 8];     // {x, y, z, -t2/2}, +8 pad
__device__ int    g_tidx  [NV + 8];
__device__ float4 g_psorted[NPTS];       // {x, y, z, orig_point_idx}
__device__ int    g_knn_idx[NPTS * KNN];
__device__ float  g_knn_d  [NPTS * KNN];

__device__ __forceinline__ int bin_of(float x) {
    return min(NB - 1, max(0, (int)((x + XLIM) * BINV)));
}

// Exact reference-rounded d2 (verified R3-R11), clamped BEFORE selection,
// packed with the original index into a scan-order-independent sortable key.
__device__ __forceinline__ u64 cand_key(float4 t, int oidx,
                                        float px, float py, float pz, float p2) {
    float t2 = -2.0f * t.w;              // exact
    float cross = __fmaf_rn(pz, t.z, __fmaf_rn(py, t.y, __fmul_rn(px, t.x)));
    float d2 = fmaxf(__fmaf_rn(-2.0f, cross, __fadd_rn(p2, t2)), 0.0f);
    return ((u64)__float_as_uint(d2) << 32) | (u64)(unsigned)oidx;
}

__device__ __forceinline__ void key_insert(u64* K, u64 key) {
    if (key < K[KNN - 1]) {
        K[KNN - 1] = key;
#pragma unroll
        for (int k = KNN - 1; k > 0; --k)
            if (K[k] < K[k - 1]) { u64 t = K[k]; K[k] = K[k - 1]; K[k - 1] = t; }
    }
}

// Dedup-merge the pair's sorted lists (keys unique per candidate; equal keys
// collapse). Safe to call repeatedly. Both lanes end with the identical merge.
__device__ __forceinline__ void merge_pair(u64* K) {
    u64 O[KNN];
#pragma unroll
    for (int k = 0; k < KNN; ++k)
        O[k] = __shfl_xor_sync(0xFFFFFFFFu, K[k], 1);
    u64 R[KNN];
    int a = 0, b = 0;
#pragma unroll
    for (int k = 0; k < KNN; ++k) {
        u64 ka = (a < KNN) ? K[a] : KSENT;
        u64 kb = (b < KNN) ? O[b] : KSENT;
        if (ka == kb)      { R[k] = ka; ++a; ++b; }
        else if (ka < kb)  { R[k] = ka; ++a; }
        else               { R[k] = kb; ++b; }
    }
#pragma unroll
    for (int k = 0; k < KNN; ++k) K[k] = R[k];
}

// ---------------------------------------------------------------------------
// Prep kernels (R9-verified)
// ---------------------------------------------------------------------------
extern "C" __global__ void k_zero() {
    int i = blockIdx.x * blockDim.x + threadIdx.x;
    if (i < NB) { g_tbcnt[i] = 0; g_pbcnt[i] = 0; }
}

extern "C" __global__ void k_hist(const float* __restrict__ tpts,
                                  const float* __restrict__ pts) {
    int i = blockIdx.x * blockDim.x + threadIdx.x;
    if (i < NV)   atomicAdd(&g_tbcnt[bin_of(tpts[3 * i])], 1);
    if (i < NPTS) atomicAdd(&g_pbcnt[bin_of(pts [3 * i])], 1);
}

extern "C" __global__ void __launch_bounds__(1024) k_scan() {
    __shared__ int sA[NB], sB[NB];
    const int t = threadIdx.x;
#pragma unroll 1
    for (int w = 0; w < 2; ++w) {
        const int* cnt = w ? g_pbcnt : g_tbcnt;
        int* start = w ? g_pbstart : g_tbstart;
        int* cur   = w ? g_pbcur   : g_tbcur;
        int c = cnt[t];
        sA[t] = c; __syncthreads();
        int *src = sA, *dst = sB;
        for (int off = 1; off < NB; off <<= 1) {
            int v = src[t] + ((t >= off) ? src[t - off] : 0);
            dst[t] = v; __syncthreads();
            int* tmp = src; src = dst; dst = tmp;
        }
        start[t] = src[t] - c; cur[t] = src[t] - c;
        if (t == NB - 1) start[NB] = src[t];
        __syncthreads();
    }
}

extern "C" __global__ void k_scatter(const float* __restrict__ tpts,
                                     const float* __restrict__ pts) {
    int i = blockIdx.x * blockDim.x + threadIdx.x;
    if (i < NV) {
        float x = tpts[3*i], y = tpts[3*i+1], z = tpts[3*i+2];
        float t2 = __fadd_rn(__fadd_rn(__fmul_rn(x, x), __fmul_rn(y, y)),
                             __fmul_rn(z, z));
        int pos = atomicAdd(&g_tbcur[bin_of(x)], 1);
        g_tsorted[pos] = make_float4(x, y, z, -0.5f * t2);
        g_tidx[pos] = i;
    }
    if (i < NV + 8 && i >= NV) {
        g_tsorted[i] = make_float4(0.f, 0.f, 0.f, -INFINITY);
        g_tidx[i] = 0;
    }
    if (i < NPTS) {
        float x = pts[3*i], y = pts[3*i+1], z = pts[3*i+2];
        int pos = atomicAdd(&g_pbcur[bin_of(x)], 1);
        g_psorted[pos] = make_float4(x, y, z, __uint_as_float((unsigned)i));
    }
}

// ---------------------------------------------------------------------------
// Pair-split segment scan: lane parity selects alternating 8-batches.
// Screen threshold from OWN partial top-6 (>= merged d6 -> conservative).
// ---------------------------------------------------------------------------
__device__ __forceinline__ void scan_pair(
    const float4* __restrict__ base, int s, int e, int par,
    float px, float py, float pz, float p2, u64* K, float& s_thresh)
{
    int bcnt = 0;
#pragma unroll 1
    for (int v0 = s + (par << 3); v0 < e; v0 += 16) {
        float sc[8];
#pragma unroll
        for (int i = 0; i < 8; ++i) {
            float4 t = base[v0 + i];                 // pad covers overread
            float v = fmaf(pz, t.z, fmaf(py, t.y, fmaf(px, t.x, t.w)));
            sc[i] = (v0 + i < e) ? v : -INFINITY;
        }
        float m = fmaxf(fmaxf(fmaxf(sc[0], sc[1]), fmaxf(sc[2], sc[3])),
                        fmaxf(fmaxf(sc[4], sc[5]), fmaxf(sc[6], sc[7])));
        if (m > s_thresh) {
            unsigned pm = 0;
#pragma unroll
            for (int i = 0; i < 8; ++i)
                pm |= (sc[i] > s_thresh) ? (1u << i) : 0u;
            while (pm) {
                int i = __ffs(pm) - 1; pm &= pm - 1;
                int gj = v0 + i;
                key_insert(K, cand_key(base[gj], __ldg(&g_tidx[gj]),
                                       px, py, pz, p2));
            }
        }
        if (((++bcnt) & 3) == 0 && K[KNN - 1] != KSENT) {
            float d6 = __uint_as_float((unsigned)(K[KNN - 1] >> 32));
            s_thresh = fmaf(-0.5f, d6, 0.5f * p2) - SEPS;
        }
    }
    if (K[KNN - 1] != KSENT) {
        float d6 = __uint_as_float((unsigned)(K[KNN - 1] >> 32));
        s_thresh = fmaf(-0.5f, d6, 0.5f * p2) - SEPS;
    }
}

// ---------------------------------------------------------------------------
// Kernel B: windowed KNN, 2 threads per point, CTA-staged template window.
// 256 CTAs x 256 threads, 72KB smem -> 2 CTAs/SM -> one wave, 4 warps/SMSP.
// ---------------------------------------------------------------------------
extern "C" __global__ void __launch_bounds__(256, 2)
k_knn()
{
    extern __shared__ float4 sw[];       // WCAP + 8
    __shared__ int sSE[2];

    const int tid = threadIdx.x;
    const int n0  = blockIdx.x * 128;

    if (tid == 0) {
        float xf = g_psorted[n0].x, xl = g_psorted[n0 + 127].x;
        int blo = bin_of(xf - PAD), bhi = bin_of(xl + PAD);
        int S = g_tbstart[blo], E = g_tbstart[bhi + 1];
        if (E - S > WCAP) {              // rare central clamp
            int mid = (S + E) >> 1;
            S = mid - WCAP / 2; E = S + WCAP;
        }
        sSE[0] = S; sSE[1] = E;
    }
    __syncthreads();
    const int S = sSE[0], E = sSE[1];
    for (int i = tid; i < E - S; i += 256) sw[i] = g_tsorted[S + i];
    if (tid < 8) sw[E - S + tid] = make_float4(0.f, 0.f, 0.f, -INFINITY);
    __syncthreads();
    const float4* swm = sw - S;          // indexed by global template slot

    const int n   = n0 + (tid >> 1);
    const int par = tid & 1;
    float4 P = g_psorted[n];
    float px = P.x, py = P.y, pz = P.z;
    unsigned pid = __float_as_uint(P.w);
    float p2 = __fadd_rn(__fadd_rn(__fmul_rn(px, px), __fmul_rn(py, py)),
                         __fmul_rn(pz, pz));

    // warp x-hull (16 distinct points; pair lanes duplicate harmlessly)
    float xlo = px, xhi = px;
#pragma unroll
    for (int off = 16; off >= 1; off >>= 1) {
        xlo = fminf(xlo, __shfl_xor_sync(0xFFFFFFFFu, xlo, off));
        xhi = fmaxf(xhi, __shfl_xor_sync(0xFFFFFFFFu, xhi, off));
    }

    u64 K[KNN];
#pragma unroll
    for (int k = 0; k < KNN; ++k) K[k] = KSENT;
    float s_thresh = -INFINITY;

    float delta = DELTA0;
    int blo = bin_of(xlo - delta);
    int bhi = bin_of(xhi + delta);
    {
        int s = __ldg(&g_tbstart[blo]), e = __ldg(&g_tbstart[bhi + 1]);
        if (s >= S && e <= E)
            scan_pair(swm, s, e, par, px, py, pz, p2, K, s_thresh);
        else
            scan_pair(g_tsorted, s, e, par, px, py, pz, p2, K, s_thresh);
    }

#pragma unroll 1
    for (int it = 0; it < 16; ++it) {
        merge_pair(K);                   // true top-6 over scanned window
        float bxa = (blo == 0)      ? -1e15f : (float)blo       * BW - XLIM;
        float bxb = (bhi == NB - 1) ?  1e15f : (float)(bhi + 1) * BW - XLIM;
        float bound = fminf(px - bxa, bxb - px);
        float d6 = __uint_as_float((unsigned)(K[KNN - 1] >> 32));
        bool done = (K[KNN - 1] != KSENT) && (d6 <= 0.998f * bound * bound);
        if (__all_sync(0xFFFFFFFFu, done)) break;

        delta *= 2.0f;
        int nblo = bin_of(xlo - delta);
        int nbhi = bin_of(xhi + delta);
        if (nblo < blo) {
            int s = __ldg(&g_tbstart[nblo]), e = __ldg(&g_tbstart[blo]);
            if (s >= S && e <= E)
                scan_pair(swm, s, e, par, px, py, pz, p2, K, s_thresh);
            else
                scan_pair(g_tsorted, s, e, par, px, py, pz, p2, K, s_thresh);
        }
        if (nbhi > bhi) {
            int s = __ldg(&g_tbstart[bhi + 1]), e = __ldg(&g_tbstart[nbhi + 1]);
            if (s >= S && e <= E)
                scan_pair(swm, s, e, par, px, py, pz, p2, K, s_thresh);
            else
                scan_pair(g_tsorted, s, e, par, px, py, pz, p2, K, s_thresh);
        }
        blo = nblo; bhi = nbhi;
    }
    merge_pair(K);                       // dedup-safe; covers loop-exhaust exit

    if (par == 0) {
#pragma unroll
        for (int k = 0; k < KNN; ++k) {
            g_knn_idx[pid * KNN + k] = (int)(unsigned)(K[k] & 0xFFFFFFFFull);
            g_knn_d  [pid * KNN + k] = __uint_as_float((unsigned)(K[k] >> 32));
        }
    }
}

// ---------------------------------------------------------------------------
// Epilogue (unchanged, measured 17us). One warp = one point.
// ---------------------------------------------------------------------------
extern "C" __global__ void __launch_bounds__(256)
epilogue_kernel(const float* __restrict__ lbs,   // (V,55)
                const float* __restrict__ vt,    // (V,16)
                float* __restrict__ out)         // [N dist | N*16 transform]
{
    int gwarp = (blockIdx.x * blockDim.x + threadIdx.x) >> 5;
    int lane  = threadIdx.x & 31;

    int   idx[KNN];
    float d[KNN];
#pragma unroll
    for (int k = 0; k < KNN; ++k) {
        idx[k] = g_knn_idx[gwarp * KNN + k];
        d[k]   = g_knn_d  [gwarp * KNN + k];
    }

    const float* w0row = lbs + (long)idx[0] * NJ;
    float w0a = w0row[lane];
    float w0b = (lane < NJ - 32) ? w0row[lane + 32] : 0.0f;

    float conf[KNN];
    conf[0] = 1.0f;
#pragma unroll
    for (int k = 1; k < KNN; ++k) {
        const float* wr = lbs + (long)idx[k] * NJ;
        float a = fabsf(wr[lane] - w0a);
        if (lane < NJ - 32) a += fabsf(wr[lane + 32] - w0b);
#pragma unroll
        for (int off = 16; off >= 1; off >>= 1)
            a += __shfl_xor_sync(0xFFFFFFFFu, a, off);
        conf[k] = (expf(-a * (1.0f / 0.02f)) > 0.9f) ? 1.0f : 0.0f;
    }

    float w[KNN];
    float wsum = 0.0f;
#pragma unroll
    for (int k = 0; k < KNN; ++k) {
        w[k] = expf(-d[k]) * conf[k];
        wsum += w[k];
    }
    float inv = 1.0f / wsum;

    float xd  = 0.0f;
    float acc = 0.0f;
#pragma unroll
    for (int k = 0; k < KNN; ++k) {
        float wk = w[k] * inv;
        xd = fmaf(wk, d[k], xd);
        if (lane < 16)
            acc = fmaf(wk, vt[(long)idx[k] * 16 + lane], acc);
    }

    if (lane == 0) out[gwarp] = xd;
    if (lane < 16) out[NPTS + gwarp * 16 + lane] = acc;
}

// ---------------------------------------------------------------------------
// Launch. Inputs: lbs_weights, verts_transform, points, template_points, K.
// ---------------------------------------------------------------------------
extern "C" void kernel_launch(void* const* d_in, const int* in_sizes, int n_in,
                              void* d_out, int out_size)
{
    const float* lbs  = (const float*)d_in[0];
    const float* vt   = (const float*)d_in[1];
    const float* pts  = (const float*)d_in[2];
    const float* tpts = (const float*)d_in[3];
    float* out = (float*)d_out;

    const int smem_bytes = (WCAP + 8) * (int)sizeof(float4);   // 73856
    cudaFuncSetAttribute(k_knn,
                         cudaFuncAttributeMaxDynamicSharedMemorySize,
                         smem_bytes);

    k_zero<<<(NB + 255) / 256, 256>>>();
    k_hist<<<(NPTS + 255) / 256, 256>>>(tpts, pts);
    k_scan<<<1, 1024>>>();
    k_scatter<<<(NPTS + 255) / 256, 256>>>(tpts, pts);
    k_knn<<<NPTS / 128, 256, smem_bytes>>>();
    epilogue_kernel<<<(NPTS * 32) / 256, 256>>>(lbs, vt, out);
}

// round 13
// speedup vs baseline: 4.3059x; 1.3780x over previous
#include <cuda_runtime.h>
#include <cuda_bf16.h>
#include <math.h>

// Problem constants (fixed by setup_inputs)
#define NPTS 32768
#define NV   10475
#define NJ   55
#define KNN  6

// 2D (x,y) binning (R10-verified prep)
#define NBX  128
#define NBY  128
#define NB2  (NBX * NBY)         // 16384
#define BW   0.15625f            // 20/128, exact in fp32
#define BINV2 6.4f
#define XLIM 10.0f
#define SEPS 1e-3f               // screen slack in s-units
#define DELTA0 0.36f             // ~= sqrt(median d6): first vote often passes

typedef unsigned long long u64;
#define KSENT 0xFFFFFFFFFFFFFFFFull

// Scratch (no cudaMalloc allowed).
__device__ int    g_tcnt[NB2], g_tstart[NB2 + 1], g_tcur[NB2];
__device__ int    g_pcnt[NB2], g_pstart[NB2 + 1], g_pcur[NB2];
__device__ float4 g_tsorted[NV + 8];     // {x, y, z, -t2/2}
__device__ int    g_tidx  [NV + 8];
__device__ float4 g_psorted[NPTS];       // {x, y, z, orig_point_idx}
__device__ int    g_knn_idx[NPTS * KNN];
__device__ float  g_knn_d  [NPTS * KNN];

__device__ __forceinline__ int bin1(float x) {
    return min(NBX - 1, max(0, (int)((x + XLIM) * BINV2)));
}

// Exact reference-rounded d2 (verified R3-R12), clamped BEFORE selection,
// packed with the original index into a scan-order-independent sortable key.
__device__ __forceinline__ u64 cand_key(float4 t, int oidx,
                                        float px, float py, float pz, float p2) {
    float t2 = -2.0f * t.w;              // exact
    float cross = __fmaf_rn(pz, t.z, __fmaf_rn(py, t.y, __fmul_rn(px, t.x)));
    float d2 = fmaxf(__fmaf_rn(-2.0f, cross, __fadd_rn(p2, t2)), 0.0f);
    return ((u64)__float_as_uint(d2) << 32) | (u64)(unsigned)oidx;
}

__device__ __forceinline__ void key_insert(u64* K, u64 key) {
    if (key < K[KNN - 1]) {
        K[KNN - 1] = key;
#pragma unroll
        for (int k = KNN - 1; k > 0; --k)
            if (K[k] < K[k - 1]) { u64 t = K[k]; K[k] = K[k - 1]; K[k - 1] = t; }
    }
}

// ---------------------------------------------------------------------------
// Prep kernels (R10-verified)
// ---------------------------------------------------------------------------
extern "C" __global__ void k_zero() {
    int i = blockIdx.x * blockDim.x + threadIdx.x;
    if (i < NB2) { g_tcnt[i] = 0; g_pcnt[i] = 0; }
}

extern "C" __global__ void k_hist(const float* __restrict__ tpts,
                                  const float* __restrict__ pts) {
    int i = blockIdx.x * blockDim.x + threadIdx.x;
    if (i < NV) {
        int bx = bin1(tpts[3*i]), by = bin1(tpts[3*i+1]);
        atomicAdd(&g_tcnt[bx * NBY + by], 1);
    }
    if (i < NPTS) {
        int kx = bin1(pts[3*i]), ky = bin1(pts[3*i+1]);
        if (kx & 1) ky = NBY - 1 - ky;           // serpentine for warp locality
        atomicAdd(&g_pcnt[kx * NBY + ky], 1);
    }
}

extern "C" __global__ void __launch_bounds__(1024) k_scan() {
    __shared__ int sA[1024], sB[1024];
    const int t = threadIdx.x;
    const int C = NB2 / 1024;                    // 16 cells per thread
#pragma unroll 1
    for (int w = 0; w < 2; ++w) {
        const int* cnt = w ? g_pcnt : g_tcnt;
        int* start = w ? g_pstart : g_tstart;
        int* cur   = w ? g_pcur   : g_tcur;
        int sum = 0;
        for (int i = 0; i < C; ++i) sum += cnt[t * C + i];
        sA[t] = sum; __syncthreads();
        int *src = sA, *dst = sB;
        for (int off = 1; off < 1024; off <<= 1) {
            int v = src[t] + ((t >= off) ? src[t - off] : 0);
            dst[t] = v; __syncthreads();
            int* tmp = src; src = dst; dst = tmp;
        }
        int run = src[t] - sum;
        for (int i = 0; i < C; ++i) {
            int id = t * C + i;
            start[id] = run; cur[id] = run;
            run += cnt[id];
        }
        if (t == 1023) start[NB2] = run;
        __syncthreads();
    }
}

extern "C" __global__ void k_scatter(const float* __restrict__ tpts,
                                     const float* __restrict__ pts) {
    int i = blockIdx.x * blockDim.x + threadIdx.x;
    if (i < NV) {
        float x = tpts[3*i], y = tpts[3*i+1], z = tpts[3*i+2];
        float t2 = __fadd_rn(__fadd_rn(__fmul_rn(x, x), __fmul_rn(y, y)),
                             __fmul_rn(z, z));
        int pos = atomicAdd(&g_tcur[bin1(x) * NBY + bin1(y)], 1);
        g_tsorted[pos] = make_float4(x, y, z, -0.5f * t2);
        g_tidx[pos] = i;
    }
    if (i >= NV && i < NV + 8) {                 // pad
        g_tsorted[i] = make_float4(0.f, 0.f, 0.f, -INFINITY);
        g_tidx[i] = 0;
    }
    if (i < NPTS) {
        float x = pts[3*i], y = pts[3*i+1], z = pts[3*i+2];
        int kx = bin1(x), ky = bin1(y);
        if (kx & 1) ky = NBY - 1 - ky;
        int pos = atomicAdd(&g_pcur[kx * NBY + ky], 1);
        g_psorted[pos] = make_float4(x, y, z, __uint_as_float((unsigned)i));
    }
}

// ---------------------------------------------------------------------------
// Contiguous segment scan with screen (R4/R9/R10-verified machinery).
// ---------------------------------------------------------------------------
__device__ __forceinline__ void scan_seg(
    const float4* __restrict__ st, const int* __restrict__ stidx,
    int s, int e, float px, float py, float pz, float p2,
    u64* K, float& s_thresh)
{
#pragma unroll 1
    for (int v0 = s; v0 < e; ) {
        const int ce = min(v0 + 64, e);
#pragma unroll 1
        for (; v0 < ce; v0 += 8) {
            float sc[8];
#pragma unroll
            for (int i = 0; i < 8; ++i) {
                float4 t = st[v0 + i];
                float v = fmaf(pz, t.z, fmaf(py, t.y, fmaf(px, t.x, t.w)));
                sc[i] = (v0 + i < ce) ? v : -INFINITY;
            }
            float m = fmaxf(fmaxf(fmaxf(sc[0], sc[1]), fmaxf(sc[2], sc[3])),
                            fmaxf(fmaxf(sc[4], sc[5]), fmaxf(sc[6], sc[7])));
            if (m > s_thresh) {
                unsigned pm = 0;
#pragma unroll
                for (int i = 0; i < 8; ++i)
                    pm |= (sc[i] > s_thresh) ? (1u << i) : 0u;
                while (pm) {
                    int i = __ffs(pm) - 1; pm &= pm - 1;
                    key_insert(K, cand_key(st[v0 + i], stidx[v0 + i],
                                           px, py, pz, p2));
                }
            }
        }
        if (K[KNN - 1] != KSENT) {
            float d6 = __uint_as_float((unsigned)(K[KNN - 1] >> 32));
            s_thresh = fmaf(-0.5f, d6, 0.5f * p2) - SEPS;
        }
    }
}

// ---------------------------------------------------------------------------
// Kernel B: 2D-windowed KNN; delta0 sized to typical sqrt(d6); at most one
// adaptive extension (warp-max need) in the common case.
// ---------------------------------------------------------------------------
extern "C" __global__ void __launch_bounds__(256, 1)
k_knn()
{
    extern __shared__ char smem[];
    float4* st    = (float4*)smem;               // NV+8
    int*    stidx = (int*)(st + NV + 8);         // NV+8

    for (int i = threadIdx.x; i < NV + 8; i += 256) {
        st[i] = g_tsorted[i]; stidx[i] = g_tidx[i];
    }
    __syncthreads();

    const int n = blockIdx.x * 256 + threadIdx.x;
    float4 P = g_psorted[n];
    float px = P.x, py = P.y, pz = P.z;
    unsigned pid = __float_as_uint(P.w);
    float p2 = __fadd_rn(__fadd_rn(__fmul_rn(px, px), __fmul_rn(py, py)),
                         __fmul_rn(pz, pz));

    // warp (x,y) hull
    float xlo = px, xhi = px, ylo = py, yhi = py;
#pragma unroll
    for (int off = 16; off >= 1; off >>= 1) {
        xlo = fminf(xlo, __shfl_xor_sync(0xFFFFFFFFu, xlo, off));
        xhi = fmaxf(xhi, __shfl_xor_sync(0xFFFFFFFFu, xhi, off));
        ylo = fminf(ylo, __shfl_xor_sync(0xFFFFFFFFu, ylo, off));
        yhi = fmaxf(yhi, __shfl_xor_sync(0xFFFFFFFFu, yhi, off));
    }

    u64 K[KNN];
#pragma unroll
    for (int k = 0; k < KNN; ++k) K[k] = KSENT;
    float s_thresh = -INFINITY;

    float delta = DELTA0;
    int bxlo = bin1(xlo - delta), bxhi = bin1(xhi + delta);
    int bylo = bin1(ylo - delta), byhi = bin1(yhi + delta);

    for (int bx = bxlo; bx <= bxhi; ++bx) {
        int s = __ldg(&g_tstart[bx * NBY + bylo]);
        int e = __ldg(&g_tstart[bx * NBY + byhi + 1]);
        scan_seg(st, stidx, s, e, px, py, pz, p2, K, s_thresh);
    }

#pragma unroll 1
    for (int it = 0; it < 12; ++it) {
        // Certification: unscanned templates are outside the x- or y-window;
        // clamped grid edges contribute +inf.
        float bx_lo = (bxlo == 0)       ? 1e15f : px - ((float)bxlo * BW - XLIM);
        float bx_hi = (bxhi == NBX - 1) ? 1e15f : ((float)(bxhi + 1) * BW - XLIM) - px;
        float by_lo = (bylo == 0)       ? 1e15f : py - ((float)bylo * BW - XLIM);
        float by_hi = (byhi == NBY - 1) ? 1e15f : ((float)(byhi + 1) * BW - XLIM) - py;
        float bound = fminf(fminf(bx_lo, bx_hi), fminf(by_lo, by_hi));
        float d6 = __uint_as_float((unsigned)(K[KNN - 1] >> 32));
        bool have6 = (K[KNN - 1] != KSENT);
        bool done = have6 && (d6 <= 0.998f * bound * bound);
        if (__all_sync(0xFFFFFFFFu, done)) break;

        // Adaptive requirement: lane certifies once window half-width >= sqrt(d6).
        float need = have6 ? (__fsqrt_rn(d6) * 1.002f) : (delta * 2.0f);
#pragma unroll
        for (int off = 16; off >= 1; off >>= 1)
            need = fmaxf(need, __shfl_xor_sync(0xFFFFFFFFu, need, off));
        delta = fmaxf(need, delta + BW);        // monotone growth >= 1 bin

        int nbxlo = bin1(xlo - delta), nbxhi = bin1(xhi + delta);
        int nbylo = bin1(ylo - delta), nbyhi = bin1(yhi + delta);

        // new x strips: full new y-range
        for (int bx = nbxlo; bx < bxlo; ++bx) {
            int s = __ldg(&g_tstart[bx * NBY + nbylo]);
            int e = __ldg(&g_tstart[bx * NBY + nbyhi + 1]);
            scan_seg(st, stidx, s, e, px, py, pz, p2, K, s_thresh);
        }
        for (int bx = bxhi + 1; bx <= nbxhi; ++bx) {
            int s = __ldg(&g_tstart[bx * NBY + nbylo]);
            int e = __ldg(&g_tstart[bx * NBY + nbyhi + 1]);
            scan_seg(st, stidx, s, e, px, py, pz, p2, K, s_thresh);
        }
        // y extensions on the old x strip
        if (nbylo < bylo)
            for (int bx = bxlo; bx <= bxhi; ++bx) {
                int s = __ldg(&g_tstart[bx * NBY + nbylo]);
                int e = __ldg(&g_tstart[bx * NBY + bylo]);
                scan_seg(st, stidx, s, e, px, py, pz, p2, K, s_thresh);
            }
        if (nbyhi > byhi)
            for (int bx = bxlo; bx <= bxhi; ++bx) {
                int s = __ldg(&g_tstart[bx * NBY + byhi + 1]);
                int e = __ldg(&g_tstart[bx * NBY + nbyhi + 1]);
                scan_seg(st, stidx, s, e, px, py, pz, p2, K, s_thresh);
            }
        bxlo = nbxlo; bxhi = nbxhi; bylo = nbylo; byhi = nbyhi;
    }

#pragma unroll
    for (int k = 0; k < KNN; ++k) {
        g_knn_idx[pid * KNN + k] = (int)(unsigned)(K[k] & 0xFFFFFFFFull);
        g_knn_d  [pid * KNN + k] = __uint_as_float((unsigned)(K[k] >> 32));
    }
}

// ---------------------------------------------------------------------------
// Epilogue (unchanged, measured 17us). One warp = one point.
// ---------------------------------------------------------------------------
extern "C" __global__ void __launch_bounds__(256)
epilogue_kernel(const float* __restrict__ lbs,   // (V,55)
                const float* __restrict__ vt,    // (V,16)
                float* __restrict__ out)         // [N dist | N*16 transform]
{
    int gwarp = (blockIdx.x * blockDim.x + threadIdx.x) >> 5;
    int lane  = threadIdx.x & 31;

    int   idx[KNN];
    float d[KNN];
#pragma unroll
    for (int k = 0; k < KNN; ++k) {
        idx[k] = g_knn_idx[gwarp * KNN + k];
        d[k]   = g_knn_d  [gwarp * KNN + k];
    }

    const float* w0row = lbs + (long)idx[0] * NJ;
    float w0a = w0row[lane];
    float w0b = (lane < NJ - 32) ? w0row[lane + 32] : 0.0f;

    float conf[KNN];
    conf[0] = 1.0f;
#pragma unroll
    for (int k = 1; k < KNN; ++k) {
        const float* wr = lbs + (long)idx[k] * NJ;
        float a = fabsf(wr[lane] - w0a);
        if (lane < NJ - 32) a += fabsf(wr[lane + 32] - w0b);
#pragma unroll
        for (int off = 16; off >= 1; off >>= 1)
            a += __shfl_xor_sync(0xFFFFFFFFu, a, off);
        conf[k] = (expf(-a * (1.0f / 0.02f)) > 0.9f) ? 1.0f : 0.0f;
    }

    float w[KNN];
    float wsum = 0.0f;
#pragma unroll
    for (int k = 0; k < KNN; ++k) {
        w[k] = expf(-d[k]) * conf[k];
        wsum += w[k];
    }
    float inv = 1.0f / wsum;

    float xd  = 0.0f;
    float acc = 0.0f;
#pragma unroll
    for (int k = 0; k < KNN; ++k) {
        float wk = w[k] * inv;
        xd = fmaf(wk, d[k], xd);
        if (lane < 16)
            acc = fmaf(wk, vt[(long)idx[k] * 16 + lane], acc);
    }

    if (lane == 0) out[gwarp] = xd;
    if (lane < 16) out[NPTS + gwarp * 16 + lane] = acc;
}

// ---------------------------------------------------------------------------
// Launch. Inputs: lbs_weights, verts_transform, points, template_points, K.
// ---------------------------------------------------------------------------
extern "C" void kernel_launch(void* const* d_in, const int* in_sizes, int n_in,
                              void* d_out, int out_size)
{
    const float* lbs  = (const float*)d_in[0];
    const float* vt   = (const float*)d_in[1];
    const float* pts  = (const float*)d_in[2];
    const float* tpts = (const float*)d_in[3];
    float* out = (float*)d_out;

    const int smem_bytes = (NV + 8) * 16 + (NV + 8) * 4;   // ~210 KB
    cudaFuncSetAttribute(k_knn,
                         cudaFuncAttributeMaxDynamicSharedMemorySize,
                         smem_bytes);

    k_zero<<<(NB2 + 255) / 256, 256>>>();
    k_hist<<<(NPTS + 255) / 256, 256>>>(tpts, pts);
    k_scan<<<1, 1024>>>();
    k_scatter<<<(NPTS + 255) / 256, 256>>>(tpts, pts);
    k_knn<<<NPTS / 256, 256, smem_bytes>>>();
    epilogue_kernel<<<(NPTS * 32) / 256, 256>>>(lbs, vt, out);
}

// round 14
// speedup vs baseline: 4.6547x; 1.0810x over previous
#include <cuda_runtime.h>
#include <cuda_bf16.h>
#include <math.h>

// Problem constants (fixed by setup_inputs)
#define NPTS 32768
#define NV   10475
#define NJ   55
#define KNN  6

// 2D (x,y) binning (R10/R13-verified prep)
#define NBX  128
#define NBY  128
#define NB2  (NBX * NBY)         // 16384
#define BW   0.15625f            // 20/128, exact in fp32
#define BINV2 6.4f
#define XLIM 10.0f
#define SEPS 1e-3f               // screen slack in s-units
#define DELTA0 0.36f             // ~= sqrt(median d6)

typedef unsigned long long u64;
#define KSENT 0xFFFFFFFFFFFFFFFFull

// Scratch (no cudaMalloc allowed).
__device__ int    g_tcnt[NB2], g_tstart[NB2 + 1], g_tcur[NB2];
__device__ int    g_pcnt[NB2], g_pstart[NB2 + 1], g_pcur[NB2];
__device__ float4 g_tsorted[NV + 16];    // {x, y, z, -t2/2}
__device__ int    g_tidx  [NV + 16];
__device__ float4 g_psorted[NPTS];       // {x, y, z, orig_point_idx}
__device__ int    g_knn_idx[NPTS * KNN];
__device__ float  g_knn_d  [NPTS * KNN];

__device__ __forceinline__ int bin1(float x) {
    return min(NBX - 1, max(0, (int)((x + XLIM) * BINV2)));
}

// Exact reference-rounded d2 (verified R3-R13), clamped BEFORE selection,
// packed with the original index into a scan-order-independent sortable key.
__device__ __forceinline__ u64 cand_key(float4 t, int oidx,
                                        float px, float py, float pz, float p2) {
    float t2 = -2.0f * t.w;              // exact
    float cross = __fmaf_rn(pz, t.z, __fmaf_rn(py, t.y, __fmul_rn(px, t.x)));
    float d2 = fmaxf(__fmaf_rn(-2.0f, cross, __fadd_rn(p2, t2)), 0.0f);
    return ((u64)__float_as_uint(d2) << 32) | (u64)(unsigned)oidx;
}

__device__ __forceinline__ void key_insert(u64* K, u64 key) {
    if (key < K[KNN - 1]) {
        K[KNN - 1] = key;
#pragma unroll
        for (int k = KNN - 1; k > 0; --k)
            if (K[k] < K[k - 1]) { u64 t = K[k]; K[k] = K[k - 1]; K[k - 1] = t; }
    }
}

// Dedup-merge the pair's sorted lists (keys unique per candidate; equal keys
// collapse). Safe to call repeatedly (idempotent on merged lists).
__device__ __forceinline__ void merge_pair(u64* K) {
    u64 O[KNN];
#pragma unroll
    for (int k = 0; k < KNN; ++k)
        O[k] = __shfl_xor_sync(0xFFFFFFFFu, K[k], 1);
    u64 R[KNN];
    int a = 0, b = 0;
#pragma unroll
    for (int k = 0; k < KNN; ++k) {
        u64 ka = (a < KNN) ? K[a] : KSENT;
        u64 kb = (b < KNN) ? O[b] : KSENT;
        if (ka == kb)      { R[k] = ka; ++a; ++b; }
        else if (ka < kb)  { R[k] = ka; ++a; }
        else               { R[k] = kb; ++b; }
    }
#pragma unroll
    for (int k = 0; k < KNN; ++k) K[k] = R[k];
}

// ---------------------------------------------------------------------------
// Prep kernels (R10/R13-verified)
// ---------------------------------------------------------------------------
extern "C" __global__ void k_zero() {
    int i = blockIdx.x * blockDim.x + threadIdx.x;
    if (i < NB2) { g_tcnt[i] = 0; g_pcnt[i] = 0; }
}

extern "C" __global__ void k_hist(const float* __restrict__ tpts,
                                  const float* __restrict__ pts) {
    int i = blockIdx.x * blockDim.x + threadIdx.x;
    if (i < NV) {
        int bx = bin1(tpts[3*i]), by = bin1(tpts[3*i+1]);
        atomicAdd(&g_tcnt[bx * NBY + by], 1);
    }
    if (i < NPTS) {
        int kx = bin1(pts[3*i]), ky = bin1(pts[3*i+1]);
        if (kx & 1) ky = NBY - 1 - ky;           // serpentine for warp locality
        atomicAdd(&g_pcnt[kx * NBY + ky], 1);
    }
}

extern "C" __global__ void __launch_bounds__(1024) k_scan() {
    __shared__ int sA[1024], sB[1024];
    const int t = threadIdx.x;
    const int C = NB2 / 1024;                    // 16 cells per thread
#pragma unroll 1
    for (int w = 0; w < 2; ++w) {
        const int* cnt = w ? g_pcnt : g_tcnt;
        int* start = w ? g_pstart : g_tstart;
        int* cur   = w ? g_pcur   : g_tcur;
        int sum = 0;
        for (int i = 0; i < C; ++i) sum += cnt[t * C + i];
        sA[t] = sum; __syncthreads();
        int *src = sA, *dst = sB;
        for (int off = 1; off < 1024; off <<= 1) {
            int v = src[t] + ((t >= off) ? src[t - off] : 0);
            dst[t] = v; __syncthreads();
            int* tmp = src; src = dst; dst = tmp;
        }
        int run = src[t] - sum;
        for (int i = 0; i < C; ++i) {
            int id = t * C + i;
            start[id] = run; cur[id] = run;
            run += cnt[id];
        }
        if (t == 1023) start[NB2] = run;
        __syncthreads();
    }
}

extern "C" __global__ void k_scatter(const float* __restrict__ tpts,
                                     const float* __restrict__ pts) {
    int i = blockIdx.x * blockDim.x + threadIdx.x;
    if (i < NV) {
        float x = tpts[3*i], y = tpts[3*i+1], z = tpts[3*i+2];
        float t2 = __fadd_rn(__fadd_rn(__fmul_rn(x, x), __fmul_rn(y, y)),
                             __fmul_rn(z, z));
        int pos = atomicAdd(&g_tcur[bin1(x) * NBY + bin1(y)], 1);
        g_tsorted[pos] = make_float4(x, y, z, -0.5f * t2);
        g_tidx[pos] = i;
    }
    if (i >= NV && i < NV + 16) {                // pad
        g_tsorted[i] = make_float4(0.f, 0.f, 0.f, -INFINITY);
        g_tidx[i] = 0;
    }
    if (i < NPTS) {
        float x = pts[3*i], y = pts[3*i+1], z = pts[3*i+2];
        int kx = bin1(x), ky = bin1(y);
        if (kx & 1) ky = NBY - 1 - ky;
        int pos = atomicAdd(&g_pcur[kx * NBY + ky], 1);
        g_psorted[pos] = make_float4(x, y, z, __uint_as_float((unsigned)i));
    }
}

// ---------------------------------------------------------------------------
// Pair-split segment scan (R12-verified): lane parity takes alternating
// 8-batches. Screen threshold from OWN partial top-6 (conservative).
// ---------------------------------------------------------------------------
__device__ __forceinline__ void scan_pair(
    const float4* __restrict__ st, const int* __restrict__ stidx,
    int s, int e, int par,
    float px, float py, float pz, float p2, u64* K, float& s_thresh)
{
    int bcnt = 0;
#pragma unroll 1
    for (int v0 = s + (par << 3); v0 < e; v0 += 16) {
        float sc[8];
#pragma unroll
        for (int i = 0; i < 8; ++i) {
            float4 t = st[v0 + i];                   // pad covers overread
            float v = fmaf(pz, t.z, fmaf(py, t.y, fmaf(px, t.x, t.w)));
            sc[i] = (v0 + i < e) ? v : -INFINITY;
        }
        float m = fmaxf(fmaxf(fmaxf(sc[0], sc[1]), fmaxf(sc[2], sc[3])),
                        fmaxf(fmaxf(sc[4], sc[5]), fmaxf(sc[6], sc[7])));
        if (m > s_thresh) {
            unsigned pm = 0;
#pragma unroll
            for (int i = 0; i < 8; ++i)
                pm |= (sc[i] > s_thresh) ? (1u << i) : 0u;
            while (pm) {
                int i = __ffs(pm) - 1; pm &= pm - 1;
                key_insert(K, cand_key(st[v0 + i], stidx[v0 + i],
                                       px, py, pz, p2));
            }
        }
        if (((++bcnt) & 3) == 0 && K[KNN - 1] != KSENT) {
            float d6 = __uint_as_float((unsigned)(K[KNN - 1] >> 32));
            s_thresh = fmaf(-0.5f, d6, 0.5f * p2) - SEPS;
        }
    }
    if (K[KNN - 1] != KSENT) {
        float d6 = __uint_as_float((unsigned)(K[KNN - 1] >> 32));
        s_thresh = fmaf(-0.5f, d6, 0.5f * p2) - SEPS;
    }
}

// ---------------------------------------------------------------------------
// Kernel B: 2D-windowed KNN, 2 threads/point, 512-thread CTAs (4 warps/SMSP).
// Window schedule = R13 (delta0=0.36 + adaptive warp-max extension).
// ---------------------------------------------------------------------------
extern "C" __global__ void __launch_bounds__(512, 1)
k_knn()
{
    extern __shared__ char smem[];
    float4* st    = (float4*)smem;               // NV+16
    int*    stidx = (int*)(st + NV + 16);        // NV+16

    for (int i = threadIdx.x; i < NV + 16; i += 512) {
        st[i] = g_tsorted[i]; stidx[i] = g_tidx[i];
    }
    __syncthreads();

    const int n   = blockIdx.x * 256 + (threadIdx.x >> 1);
    const int par = threadIdx.x & 1;
    float4 P = g_psorted[n];
    float px = P.x, py = P.y, pz = P.z;
    unsigned pid = __float_as_uint(P.w);
    float p2 = __fadd_rn(__fadd_rn(__fmul_rn(px, px), __fmul_rn(py, py)),
                         __fmul_rn(pz, pz));

    // warp (x,y) hull (16 distinct points; pair lanes duplicate harmlessly)
    float xlo = px, xhi = px, ylo = py, yhi = py;
#pragma unroll
    for (int off = 16; off >= 1; off >>= 1) {
        xlo = fminf(xlo, __shfl_xor_sync(0xFFFFFFFFu, xlo, off));
        xhi = fmaxf(xhi, __shfl_xor_sync(0xFFFFFFFFu, xhi, off));
        ylo = fminf(ylo, __shfl_xor_sync(0xFFFFFFFFu, ylo, off));
        yhi = fmaxf(yhi, __shfl_xor_sync(0xFFFFFFFFu, yhi, off));
    }

    u64 K[KNN];
#pragma unroll
    for (int k = 0; k < KNN; ++k) K[k] = KSENT;
    float s_thresh = -INFINITY;

    float delta = DELTA0;
    int bxlo = bin1(xlo - delta), bxhi = bin1(xhi + delta);
    int bylo = bin1(ylo - delta), byhi = bin1(yhi + delta);

    for (int bx = bxlo; bx <= bxhi; ++bx) {
        int s = __ldg(&g_tstart[bx * NBY + bylo]);
        int e = __ldg(&g_tstart[bx * NBY + byhi + 1]);
        scan_pair(st, stidx, s, e, par, px, py, pz, p2, K, s_thresh);
    }

#pragma unroll 1
    for (int it = 0; it < 12; ++it) {
        merge_pair(K);                           // true top-6 over window
        float bx_lo = (bxlo == 0)       ? 1e15f : px - ((float)bxlo * BW - XLIM);
        float bx_hi = (bxhi == NBX - 1) ? 1e15f : ((float)(bxhi + 1) * BW - XLIM) - px;
        float by_lo = (bylo == 0)       ? 1e15f : py - ((float)bylo * BW - XLIM);
        float by_hi = (byhi == NBY - 1) ? 1e15f : ((float)(byhi + 1) * BW - XLIM) - py;
        float bound = fminf(fminf(bx_lo, bx_hi), fminf(by_lo, by_hi));
        float d6 = __uint_as_float((unsigned)(K[KNN - 1] >> 32));
        bool have6 = (K[KNN - 1] != KSENT);
        bool done = have6 && (d6 <= 0.998f * bound * bound);
        if (__all_sync(0xFFFFFFFFu, done)) break;

        float need = have6 ? (__fsqrt_rn(d6) * 1.002f) : (delta * 2.0f);
#pragma unroll
        for (int off = 16; off >= 1; off >>= 1)
            need = fmaxf(need, __shfl_xor_sync(0xFFFFFFFFu, need, off));
        delta = fmaxf(need, delta + BW);         // monotone growth >= 1 bin

        int nbxlo = bin1(xlo - delta), nbxhi = bin1(xhi + delta);
        int nbylo = bin1(ylo - delta), nbyhi = bin1(yhi + delta);

        for (int bx = nbxlo; bx < bxlo; ++bx) {
            int s = __ldg(&g_tstart[bx * NBY + nbylo]);
            int e = __ldg(&g_tstart[bx * NBY + nbyhi + 1]);
            scan_pair(st, stidx, s, e, par, px, py, pz, p2, K, s_thresh);
        }
        for (int bx = bxhi + 1; bx <= nbxhi; ++bx) {
            int s = __ldg(&g_tstart[bx * NBY + nbylo]);
            int e = __ldg(&g_tstart[bx * NBY + nbyhi + 1]);
            scan_pair(st, stidx, s, e, par, px, py, pz, p2, K, s_thresh);
        }
        if (nbylo < bylo)
            for (int bx = bxlo; bx <= bxhi; ++bx) {
                int s = __ldg(&g_tstart[bx * NBY + nbylo]);
                int e = __ldg(&g_tstart[bx * NBY + bylo]);
                scan_pair(st, stidx, s, e, par, px, py, pz, p2, K, s_thresh);
            }
        if (nbyhi > byhi)
            for (int bx = bxlo; bx <= bxhi; ++bx) {
                int s = __ldg(&g_tstart[bx * NBY + byhi + 1]);
                int e = __ldg(&g_tstart[bx * NBY + nbyhi + 1]);
                scan_pair(st, stidx, s, e, par, px, py, pz, p2, K, s_thresh);
            }
        bxlo = nbxlo; bxhi = nbxhi; bylo = nbylo; byhi = nbyhi;
    }
    merge_pair(K);                               // covers loop-exhaust exit

    if (par == 0) {
#pragma unroll
        for (int k = 0; k < KNN; ++k) {
            g_knn_idx[pid * KNN + k] = (int)(unsigned)(K[k] & 0xFFFFFFFFull);
            g_knn_d  [pid * KNN + k] = __uint_as_float((unsigned)(K[k] >> 32));
        }
    }
}

// ---------------------------------------------------------------------------
// Epilogue (unchanged, measured 17us). One warp = one point.
// ---------------------------------------------------------------------------
extern "C" __global__ void __launch_bounds__(256)
epilogue_kernel(const float* __restrict__ lbs,   // (V,55)
                const float* __restrict__ vt,    // (V,16)
                float* __restrict__ out)         // [N dist | N*16 transform]
{
    int gwarp = (blockIdx.x * blockDim.x + threadIdx.x) >> 5;
    int lane  = threadIdx.x & 31;

    int   idx[KNN];
    float d[KNN];
#pragma unroll
    for (int k = 0; k < KNN; ++k) {
        idx[k] = g_knn_idx[gwarp * KNN + k];
        d[k]   = g_knn_d  [gwarp * KNN + k];
    }

    const float* w0row = lbs + (long)idx[0] * NJ;
    float w0a = w0row[lane];
    float w0b = (lane < NJ - 32) ? w0row[lane + 32] : 0.0f;

    float conf[KNN];
    conf[0] = 1.0f;
#pragma unroll
    for (int k = 1; k < KNN; ++k) {
        const float* wr = lbs + (long)idx[k] * NJ;
        float a = fabsf(wr[lane] - w0a);
        if (lane < NJ - 32) a += fabsf(wr[lane + 32] - w0b);
#pragma unroll
        for (int off = 16; off >= 1; off >>= 1)
            a += __shfl_xor_sync(0xFFFFFFFFu, a, off);
        conf[k] = (expf(-a * (1.0f / 0.02f)) > 0.9f) ? 1.0f : 0.0f;
    }

    float w[KNN];
    float wsum = 0.0f;
#pragma unroll
    for (int k = 0; k < KNN; ++k) {
        w[k] = expf(-d[k]) * conf[k];
        wsum += w[k];
    }
    float inv = 1.0f / wsum;

    float xd  = 0.0f;
    float acc = 0.0f;
#pragma unroll
    for (int k = 0; k < KNN; ++k) {
        float wk = w[k] * inv;
        xd = fmaf(wk, d[k], xd);
        if (lane < 16)
            acc = fmaf(wk, vt[(long)idx[k] * 16 + lane], acc);
    }

    if (lane == 0) out[gwarp] = xd;
    if (lane < 16) out[NPTS + gwarp * 16 + lane] = acc;
}

// ---------------------------------------------------------------------------
// Launch. Inputs: lbs_weights, verts_transform, points, template_points, K.
// ---------------------------------------------------------------------------
extern "C" void kernel_launch(void* const* d_in, const int* in_sizes, int n_in,
                              void* d_out, int out_size)
{
    const float* lbs  = (const float*)d_in[0];
    const float* vt   = (const float*)d_in[1];
    const float* pts  = (const float*)d_in[2];
    const float* tpts = (const float*)d_in[3];
    float* out = (float*)d_out;

    const int smem_bytes = (NV + 16) * 16 + (NV + 16) * 4;   // ~210 KB
    cudaFuncSetAttribute(k_knn,
                         cudaFuncAttributeMaxDynamicSharedMemorySize,
                         smem_bytes);

    k_zero<<<(NB2 + 255) / 256, 256>>>();
    k_hist<<<(NPTS + 255) / 256, 256>>>(tpts, pts);
    k_scan<<<1, 1024>>>();
    k_scatter<<<(NPTS + 255) / 256, 256>>>(tpts, pts);
    k_knn<<<NPTS / 256, 512, smem_bytes>>>();
    epilogue_kernel<<<(NPTS * 32) / 256, 256>>>(lbs, vt, out);
}